// round 15
// baseline (speedup 1.0000x reference)
#include <cuda_runtime.h>
#include <cstdint>

// ---------------------------------------------------------------------------
// NormEMAVectorQuantizer (sm_103a via compute_103) — round 15
// TF32 mma.sync screen + gap test + exact fp32 fixup (float-shuffle +
// smem atomicMax reduction) + float4 k_update.
//   out = concat( z_q[262144], loss[1], token_ids[8192],
//                 new_embedding[262144], new_cluster_sizes[8192] ) = 540673 f32
// ---------------------------------------------------------------------------

#define N_VEC   8192
#define N_TOK   8192
#define CDIM    32
#define KSPL    16
#define THRESH  2.0e-3f     // >= 2 * 2^-10 rigorous tf32 dot-error bound (unit vecs)

#define OFF_ZQ    0
#define OFF_LOSS  262144
#define OFF_TOK   262145
#define OFF_EMB   270337
#define OFF_CSZ   532481

// B layout: per code 44 words (32 tf32 frag-packed -> 2x LDS.128 per chain)
#define EPKW        44
#define CODE_BYTES  176
#define NB_CODES    128
#define STAGE_BYTES (NB_CODES * CODE_BYTES)   // 22528
#define SMEM_TOTAL  (2 * STAGE_BYTES)         // 45056

// scratch (__device__ globals; no allocations allowed)
__device__ float              g_zn[N_VEC * CDIM];
__device__ uint32_t           g_qpk[N_VEC * CDIM];
__device__ uint32_t           g_epk[N_TOK * EPKW];
__device__ float              g_ekT[CDIM * N_TOK];     // fp32 codes, TRANSPOSED
__device__ unsigned long long g_t1[KSPL * N_VEC];
__device__ float              g_t2v[KSPL * N_VEC];
__device__ unsigned long long g_key[N_VEC];
__device__ int                g_fix[N_VEC];
__device__ int                g_nfix;
__device__ float              g_bins[N_TOK];
__device__ float              g_esum[N_TOK * CDIM];
__device__ float              g_loss;

// ---------------- helpers ---------------------------------------------------
static __device__ __forceinline__ uint32_t smem_u32(const void* p) {
    uint32_t a;
    asm("{ .reg .u64 t; cvta.to.shared.u64 t, %1; cvt.u32.u64 %0, t; }" : "=r"(a) : "l"(p));
    return a;
}
static __device__ __forceinline__ unsigned int ordered_u32(float v) {
    unsigned int b = __float_as_uint(v);
    return (b & 0x80000000u) ? ~b : (b | 0x80000000u);
}
static __device__ __forceinline__ float unordered_f32(unsigned int u) {
    unsigned int b = (u & 0x80000000u) ? (u & 0x7fffffffu) : ~u;
    return __uint_as_float(b);
}
static __device__ __forceinline__ uint32_t to_tf32(float x) {
    uint32_t r;
    asm("cvt.rna.tf32.f32 %0, %1;" : "=r"(r) : "f"(x));
    return r;
}
// frag-packed position: thread l4 consumes words [l4*8 .. l4*8+7]
static __device__ __forceinline__ int b_reorder(int c) {
    int kc = c >> 3, r = c & 7;
    return (r < 4) ? (r * 8 + kc * 2) : ((r - 4) * 8 + kc * 2 + 1);
}

#define MMA_TF32(D, Af, Bf)                                                   \
    asm volatile(                                                             \
        "mma.sync.aligned.m16n8k8.row.col.f32.tf32.tf32.f32 "                 \
        "{%0,%1,%2,%3}, {%4,%5,%6,%7}, {%8,%9}, {%0,%1,%2,%3};"               \
        : "+f"((D)[0]), "+f"((D)[1]), "+f"((D)[2]), "+f"((D)[3])              \
        : "r"((Af)[0]), "r"((Af)[1]), "r"((Af)[2]), "r"((Af)[3]),             \
          "r"((Bf)[0]), "r"((Bf)[1]))

// ---------------------------------------------------------------------------
// K1: fused prep — L2norm(z)+tf32 pack | embedding frag-pack | fp32
//     transpose | zero scratch.
// ---------------------------------------------------------------------------
#define NORM_BLKS 1024
#define ESPL_BLKS 1024
#define TRNS_BLKS 32
#define ZERO_ITEMS (N_TOK * CDIM + N_TOK)
#define ZERO_BLKS ((ZERO_ITEMS + 255) / 256)

__global__ __launch_bounds__(256) void k_prep(const float* __restrict__ z,
                                              const float* __restrict__ emb) {
    __shared__ float tile[256][33];
    if (blockIdx.x < NORM_BLKS) {
        int warp = threadIdx.x >> 5;
        int lane = threadIdx.x & 31;                 // channel c
        int n    = blockIdx.x * 8 + warp;
        int b    = n >> 8, hw = n & 255;
        float v  = z[b * (CDIM * 256) + lane * 256 + hw];
        float ss = v * v;
#pragma unroll
        for (int o = 16; o > 0; o >>= 1)
            ss += __shfl_xor_sync(0xffffffffu, ss, o);
        float inv = 1.0f / fmaxf(sqrtf(ss), 1e-12f);
        float x = v * inv;
        g_zn[n * CDIM + lane]  = x;
        g_qpk[n * CDIM + lane] = to_tf32(x);
    } else if (blockIdx.x < NORM_BLKS + ESPL_BLKS) {
        int i = (blockIdx.x - NORM_BLKS) * 256 + threadIdx.x;   // 0..262143
        int r = i >> 5, c = i & 31;
        g_epk[r * EPKW + b_reorder(c)] = to_tf32(emb[i]);
    } else if (blockIdx.x < NORM_BLKS + ESPL_BLKS + TRNS_BLKS) {
        int j = blockIdx.x - (NORM_BLKS + ESPL_BLKS);
        int rbase = j * 256;
#pragma unroll 4
        for (int jj = 0; jj < 32; jj++) {
            int idx = jj * 256 + threadIdx.x;         // coalesced read
            tile[idx >> 5][idx & 31] = emb[rbase * 32 + idx];
        }
        __syncthreads();
#pragma unroll
        for (int jj = 0; jj < 4; jj++) {
            int c = jj * 8 + (threadIdx.x >> 5);
#pragma unroll
            for (int inner = 0; inner < 8; inner++) {
                int r = inner * 32 + (threadIdx.x & 31);
                g_ekT[c * N_TOK + rbase + r] = tile[r][c];   // coalesced write
            }
        }
    } else {
        int i = (blockIdx.x - NORM_BLKS - ESPL_BLKS - TRNS_BLKS) * 256 + threadIdx.x;
        if (i < N_TOK * CDIM) g_esum[i] = 0.0f;
        else if (i < ZERO_ITEMS) g_bins[i - N_TOK * CDIM] = 0.0f;
        if (i == 0) { g_loss = 0.0f; g_nfix = 0; }
    }
}

// ---------------------------------------------------------------------------
// K2: TF32 mma.sync screen, ILP-4 chains, LDS.128 frags, unroll-2.
// grid (64, 16) = 1024 CTAs.
// ---------------------------------------------------------------------------
__global__ __launch_bounds__(256, 3) void k_mma() {
    extern __shared__ uint32_t smem[];
    uint32_t sbase = smem_u32(smem);
    int tid = threadIdx.x, wid = tid >> 5, lane = tid & 31;
    int g4 = lane >> 2, l4 = lane & 3;
    int qb    = blockIdx.x * 128 + wid * 16;
    int kbase = blockIdx.y * (N_TOK / KSPL);

    uint32_t A[4][4];
    {
        const uint32_t* q0 = g_qpk + (qb + g4) * CDIM;
        const uint32_t* q8 = g_qpk + (qb + g4 + 8) * CDIM;
#pragma unroll
        for (int kc = 0; kc < 4; kc++) {
            int w = kc * 8 + l4;
            A[kc][0] = q0[w];
            A[kc][1] = q8[w];
            A[kc][2] = q0[w + 4];
            A[kc][3] = q8[w + 4];
        }
    }

    float v1a = -3.4e38f, v2a = -3.4e38f; int k1a = 0;
    float v1b = -3.4e38f, v2b = -3.4e38f; int k1b = 0;

    {
        const char* src = (const char*)g_epk + (size_t)kbase * CODE_BYTES;
#pragma unroll
        for (int j = 0; j < 6; j++) {
            int idx = tid + j * 256;
            if (idx < STAGE_BYTES / 16)
                asm volatile("cp.async.ca.shared.global [%0], [%1], 16;"
                             :: "r"(sbase + idx * 16), "l"(src + idx * 16) : "memory");
        }
        asm volatile("cp.async.commit_group;" ::: "memory");
    }

    for (int nb = 0; nb < (N_TOK / KSPL) / NB_CODES; nb++) {
        asm volatile("cp.async.wait_group 0;" ::: "memory");
        __syncthreads();
        if (nb + 1 < (N_TOK / KSPL) / NB_CODES) {
            const char* src = (const char*)g_epk +
                              (size_t)(kbase + (nb + 1) * NB_CODES) * CODE_BYTES;
            uint32_t dst = sbase + ((nb + 1) & 1) * STAGE_BYTES;
#pragma unroll
            for (int j = 0; j < 6; j++) {
                int idx = tid + j * 256;
                if (idx < STAGE_BYTES / 16)
                    asm volatile("cp.async.ca.shared.global [%0], [%1], 16;"
                                 :: "r"(dst + idx * 16), "l"(src + idx * 16) : "memory");
            }
            asm volatile("cp.async.commit_group;" ::: "memory");
        }

        const uint32_t* buf = smem + (nb & 1) * (STAGE_BYTES / 4);

#pragma unroll 2
        for (int nt = 0; nt < NB_CODES / 8; nt += 4) {
            const uint32_t* r0 = buf + (nt * 8 + g4) * EPKW + l4 * 8;
            float D0[4] = {0.f, 0.f, 0.f, 0.f};
            float D1[4] = {0.f, 0.f, 0.f, 0.f};
            float D2[4] = {0.f, 0.f, 0.f, 0.f};
            float D3[4] = {0.f, 0.f, 0.f, 0.f};
            uint4 p0a = *(const uint4*)(r0);
            uint4 p0b = *(const uint4*)(r0 + 4);
            uint4 p1a = *(const uint4*)(r0 + 8  * EPKW);
            uint4 p1b = *(const uint4*)(r0 + 8  * EPKW + 4);
            uint4 p2a = *(const uint4*)(r0 + 16 * EPKW);
            uint4 p2b = *(const uint4*)(r0 + 16 * EPKW + 4);
            uint4 p3a = *(const uint4*)(r0 + 24 * EPKW);
            uint4 p3b = *(const uint4*)(r0 + 24 * EPKW + 4);
            {
                uint32_t B0[2] = {p0a.x, p0a.y};
                uint32_t B1[2] = {p1a.x, p1a.y};
                uint32_t B2[2] = {p2a.x, p2a.y};
                uint32_t B3[2] = {p3a.x, p3a.y};
                MMA_TF32(D0, A[0], B0); MMA_TF32(D1, A[0], B1);
                MMA_TF32(D2, A[0], B2); MMA_TF32(D3, A[0], B3);
            }
            {
                uint32_t B0[2] = {p0a.z, p0a.w};
                uint32_t B1[2] = {p1a.z, p1a.w};
                uint32_t B2[2] = {p2a.z, p2a.w};
                uint32_t B3[2] = {p3a.z, p3a.w};
                MMA_TF32(D0, A[1], B0); MMA_TF32(D1, A[1], B1);
                MMA_TF32(D2, A[1], B2); MMA_TF32(D3, A[1], B3);
            }
            {
                uint32_t B0[2] = {p0b.x, p0b.y};
                uint32_t B1[2] = {p1b.x, p1b.y};
                uint32_t B2[2] = {p2b.x, p2b.y};
                uint32_t B3[2] = {p3b.x, p3b.y};
                MMA_TF32(D0, A[2], B0); MMA_TF32(D1, A[2], B1);
                MMA_TF32(D2, A[2], B2); MMA_TF32(D3, A[2], B3);
            }
            {
                uint32_t B0[2] = {p0b.z, p0b.w};
                uint32_t B1[2] = {p1b.z, p1b.w};
                uint32_t B2[2] = {p2b.z, p2b.w};
                uint32_t B3[2] = {p3b.z, p3b.w};
                MMA_TF32(D0, A[3], B0); MMA_TF32(D1, A[3], B1);
                MMA_TF32(D2, A[3], B2); MMA_TF32(D3, A[3], B3);
            }

            int c0 = kbase + nb * NB_CODES + nt * 8 + l4 * 2;
            {
                float m0 = fmaxf(D0[0], D0[1]);
                float m1 = fmaxf(D1[0], D1[1]);
                float m2 = fmaxf(D2[0], D2[1]);
                float m3 = fmaxf(D3[0], D3[1]);
                float vm = fmaxf(fmaxf(m0, m1), fmaxf(m2, m3));
                if (vm > v1a) {
                    float sec; int kk;
                    if (m0 == vm) {
                        sec = fmaxf(fminf(D0[0], D0[1]), fmaxf(m1, fmaxf(m2, m3)));
                        kk = (D0[0] == vm) ? c0 : c0 + 1;
                    } else if (m1 == vm) {
                        sec = fmaxf(fminf(D1[0], D1[1]), fmaxf(m0, fmaxf(m2, m3)));
                        kk = (D1[0] == vm) ? c0 + 8 : c0 + 9;
                    } else if (m2 == vm) {
                        sec = fmaxf(fminf(D2[0], D2[1]), fmaxf(m0, fmaxf(m1, m3)));
                        kk = (D2[0] == vm) ? c0 + 16 : c0 + 17;
                    } else {
                        sec = fmaxf(fminf(D3[0], D3[1]), fmaxf(m0, fmaxf(m1, m2)));
                        kk = (D3[0] == vm) ? c0 + 24 : c0 + 25;
                    }
                    v2a = fmaxf(fmaxf(v2a, v1a), sec);
                    v1a = vm; k1a = kk;
                } else {
                    v2a = fmaxf(v2a, vm);
                }
            }
            {
                float m0 = fmaxf(D0[2], D0[3]);
                float m1 = fmaxf(D1[2], D1[3]);
                float m2 = fmaxf(D2[2], D2[3]);
                float m3 = fmaxf(D3[2], D3[3]);
                float vm = fmaxf(fmaxf(m0, m1), fmaxf(m2, m3));
                if (vm > v1b) {
                    float sec; int kk;
                    if (m0 == vm) {
                        sec = fmaxf(fminf(D0[2], D0[3]), fmaxf(m1, fmaxf(m2, m3)));
                        kk = (D0[2] == vm) ? c0 : c0 + 1;
                    } else if (m1 == vm) {
                        sec = fmaxf(fminf(D1[2], D1[3]), fmaxf(m0, fmaxf(m2, m3)));
                        kk = (D1[2] == vm) ? c0 + 8 : c0 + 9;
                    } else if (m2 == vm) {
                        sec = fmaxf(fminf(D2[2], D2[3]), fmaxf(m0, fmaxf(m1, m3)));
                        kk = (D2[2] == vm) ? c0 + 16 : c0 + 17;
                    } else {
                        sec = fmaxf(fminf(D3[2], D3[3]), fmaxf(m0, fmaxf(m1, m2)));
                        kk = (D3[2] == vm) ? c0 + 24 : c0 + 25;
                    }
                    v2b = fmaxf(fmaxf(v2b, v1b), sec);
                    v1b = vm; k1b = kk;
                } else {
                    v2b = fmaxf(v2b, vm);
                }
            }
        }
    }

#pragma unroll
    for (int d = 1; d < 4; d <<= 1) {
        float ov1; int ok1; float ov2;
        ov1 = __shfl_xor_sync(0xffffffffu, v1a, d);
        ok1 = __shfl_xor_sync(0xffffffffu, k1a, d);
        ov2 = __shfl_xor_sync(0xffffffffu, v2a, d);
        {
            bool take = (ov1 > v1a) || (ov1 == v1a && ok1 < k1a);
            float lose = take ? v1a : ov1;
            v2a = fmaxf(fmaxf(v2a, ov2), lose);
            if (take) { v1a = ov1; k1a = ok1; }
        }
        ov1 = __shfl_xor_sync(0xffffffffu, v1b, d);
        ok1 = __shfl_xor_sync(0xffffffffu, k1b, d);
        ov2 = __shfl_xor_sync(0xffffffffu, v2b, d);
        {
            bool take = (ov1 > v1b) || (ov1 == v1b && ok1 < k1b);
            float lose = take ? v1b : ov1;
            v2b = fmaxf(fmaxf(v2b, ov2), lose);
            if (take) { v1b = ov1; k1b = ok1; }
        }
    }
    if (l4 == 0) {
        int q = qb + g4;
        int sp = blockIdx.y;
        g_t1[sp * N_VEC + q] =
            ((unsigned long long)ordered_u32(v1a) << 32) |
            (unsigned int)(N_TOK - 1 - k1a);
        g_t2v[sp * N_VEC + q] = v2a;
        g_t1[sp * N_VEC + q + 8] =
            ((unsigned long long)ordered_u32(v1b) << 32) |
            (unsigned int)(N_TOK - 1 - k1b);
        g_t2v[sp * N_VEC + q + 8] = v2b;
    }
}

// ---------------------------------------------------------------------------
// K3: merge KSPL splits' top-2, gap test, build fixup list
// ---------------------------------------------------------------------------
__global__ __launch_bounds__(256) void k_merge() {
    int n = blockIdx.x * 256 + threadIdx.x;
    unsigned long long win = 0ull;
    float v2 = -3.4e38f;
#pragma unroll
    for (int s = 0; s < KSPL; s++) {
        unsigned long long t = g_t1[s * N_VEC + n];
        float tv2 = g_t2v[s * N_VEC + n];
        if (t > win) {
            v2 = fmaxf(v2, unordered_f32((unsigned int)(win >> 32)));
            win = t;
        } else {
            v2 = fmaxf(v2, unordered_f32((unsigned int)(t >> 32)));
        }
        v2 = fmaxf(v2, tv2);
    }
    float v1 = unordered_f32((unsigned int)(win >> 32));
    if (v1 - v2 < THRESH) {
        g_key[n] = 0ull;
        int i = atomicAdd(&g_nfix, 1);
        g_fix[i] = n;
    } else {
        g_key[n] = win;
    }
}

// ---------------------------------------------------------------------------
// K4: exact fp32 rescan for flagged queries.
// grid 2048 = 64 slots (16 q) x 32 chunks (256 codes). Reduction: float
// shuffle-max (5 single-word SHFLs) + smem atomicMax of the 64-bit key by
// the max-matching lanes (ties resolved by inverted-index key = first-max).
// ---------------------------------------------------------------------------
#define FIX_SLOTS 64
#define FIX_QPB   16
__global__ __launch_bounds__(128) void k_fixup() {
    __shared__ int   qid[FIX_QPB];
    __shared__ float zq[FIX_QPB][32];
    __shared__ unsigned long long qbest[FIX_QPB];
    int cnt = g_nfix;
    int chunk = blockIdx.x & 31;
    int slot  = blockIdx.x >> 5;
    if (slot * FIX_QPB >= cnt) return;
    int t = threadIdx.x;

    int ka = chunk * 256 + t;
    int kb = ka + 128;
    float ra[CDIM], rb[CDIM];
#pragma unroll
    for (int c = 0; c < CDIM; c++) {
        ra[c] = g_ekT[c * N_TOK + ka];     // lane-consecutive: coalesced
        rb[c] = g_ekT[c * N_TOK + kb];
    }

    for (int qg = slot * FIX_QPB; qg < cnt; qg += FIX_SLOTS * FIX_QPB) {
        int nq = cnt - qg;
        if (nq > FIX_QPB) nq = FIX_QPB;
        if (t < FIX_QPB) {
            qid[t]   = (t < nq) ? g_fix[qg + t] : -1;
            qbest[t] = 0ull;
        }
        __syncthreads();
#pragma unroll
        for (int j = 0; j < 4; j++) {
            int idx = t + j * 128;
            int q = idx >> 5, c = idx & 31;
            int n = qid[q];
            zq[q][c] = (n >= 0) ? g_zn[n * CDIM + c] : 0.0f;
        }
        __syncthreads();

#pragma unroll 1
        for (int q = 0; q < FIX_QPB; q += 2) {
            float sa0 = 0.f, sa1 = 0.f, sb0 = 0.f, sb1 = 0.f;
#pragma unroll
            for (int c = 0; c < CDIM; c++) {
                float za = zq[q][c];
                float zb = zq[q + 1][c];
                sa0 = fmaf(za, ra[c], sa0);
                sa1 = fmaf(za, rb[c], sa1);
                sb0 = fmaf(zb, ra[c], sb0);
                sb1 = fmaf(zb, rb[c], sb1);
            }
            // query q: pick thread-local best (tie -> smaller k = ka)
            float vA = fmaxf(sa0, sa1);
            int   kA = (sa1 > sa0) ? kb : ka;
            float mA = vA;
#pragma unroll
            for (int o = 16; o > 0; o >>= 1)
                mA = fmaxf(mA, __shfl_xor_sync(0xffffffffu, mA, o));
            if (vA == mA) {
                unsigned long long key =
                    ((unsigned long long)ordered_u32(vA) << 32) |
                    (unsigned int)(N_TOK - 1 - kA);
                atomicMax(&qbest[q], key);
            }
            // query q+1
            float vB = fmaxf(sb0, sb1);
            int   kB = (sb1 > sb0) ? kb : ka;
            float mB = vB;
#pragma unroll
            for (int o = 16; o > 0; o >>= 1)
                mB = fmaxf(mB, __shfl_xor_sync(0xffffffffu, mB, o));
            if (vB == mB) {
                unsigned long long key =
                    ((unsigned long long)ordered_u32(vB) << 32) |
                    (unsigned int)(N_TOK - 1 - kB);
                atomicMax(&qbest[q + 1], key);
            }
        }
        __syncthreads();
        if (t < FIX_QPB && qid[t] >= 0)
            atomicMax(&g_key[qid[t]], qbest[t]);
        __syncthreads();
    }
}

// ---------------------------------------------------------------------------
// K5: scatter epilogue over 262144 threads
// ---------------------------------------------------------------------------
__global__ __launch_bounds__(256) void k_scatter(const float* __restrict__ emb,
                                                 float* __restrict__ out) {
    __shared__ float red[8];
    int g  = blockIdx.x * 256 + threadIdx.x;
    int b  = g >> 13;
    int c  = (g >> 8) & 31;
    int hw = g & 255;
    int n  = b * 256 + hw;

    unsigned long long key = g_key[n];
    int bi = (N_TOK - 1) - (int)(unsigned int)(key & 0xffffffffu);

    float ev = emb[bi * CDIM + c];
    float zv = g_zn[n * CDIM + c];
    out[OFF_ZQ + g] = ev;
    if (c == 0) {
        out[OFF_TOK + n] = (float)bi;
        atomicAdd(&g_bins[bi], 1.0f);
    }
    atomicAdd(&g_esum[bi * CDIM + c], zv);

    float d = ev - zv;
    float lsum = d * d;
#pragma unroll
    for (int o = 16; o > 0; o >>= 1)
        lsum += __shfl_xor_sync(0xffffffffu, lsum, o);
    if ((threadIdx.x & 31) == 0) red[threadIdx.x >> 5] = lsum;
    __syncthreads();
    if (threadIdx.x == 0) {
        float s = 0.0f;
#pragma unroll
        for (int w = 0; w < 8; w++) s += red[w];
        atomicAdd(&g_loss, s);
    }
}

// ---------------------------------------------------------------------------
// K6: EMA codebook update, 8 threads/token (float4), + loss write
// ---------------------------------------------------------------------------
__global__ __launch_bounds__(256) void k_update(const float* __restrict__ emb,
                                                const float* __restrict__ csz,
                                                float* __restrict__ out) {
    int gtid = blockIdx.x * 256 + threadIdx.x;   // 65536 threads
    int k  = gtid >> 3;
    int l8 = gtid & 7;

    float bcount = g_bins[k];
    if (l8 == 0)
        out[OFF_CSZ + k] = csz[k] * 0.99f + 0.01f * bcount;

    bool  zero  = (bcount == 0.0f);
    float invbc = 1.0f / (zero ? 1.0f : bcount);
    float4 e4   = *(const float4*)(g_esum + k * CDIM + l8 * 4);
    float m0 = e4.x * invbc, m1 = e4.y * invbc, m2 = e4.z * invbc, m3 = e4.w * invbc;
    float ss = m0 * m0 + m1 * m1 + m2 * m2 + m3 * m3;
    ss += __shfl_xor_sync(0xffffffffu, ss, 1);
    ss += __shfl_xor_sync(0xffffffffu, ss, 2);
    ss += __shfl_xor_sync(0xffffffffu, ss, 4);
    float inv = 1.0f / fmaxf(sqrtf(ss), 1e-12f);

    float4 ev4 = *(const float4*)(emb + k * CDIM + l8 * 4);
    float en0 = zero ? ev4.x : m0 * inv;
    float en1 = zero ? ev4.y : m1 * inv;
    float en2 = zero ? ev4.z : m2 * inv;
    float en3 = zero ? ev4.w : m3 * inv;

    float v0 = ev4.x * 0.99f + 0.01f * en0;
    float v1 = ev4.y * 0.99f + 0.01f * en1;
    float v2 = ev4.z * 0.99f + 0.01f * en2;
    float v3 = ev4.w * 0.99f + 0.01f * en3;
    float s2 = v0 * v0 + v1 * v1 + v2 * v2 + v3 * v3;
    s2 += __shfl_xor_sync(0xffffffffu, s2, 1);
    s2 += __shfl_xor_sync(0xffffffffu, s2, 2);
    s2 += __shfl_xor_sync(0xffffffffu, s2, 4);
    float inv2 = 1.0f / fmaxf(sqrtf(s2), 1e-12f);

    float* dst = out + OFF_EMB + k * CDIM + l8 * 4;   // OFF_EMB odd: scalar stores
    dst[0] = v0 * inv2;
    dst[1] = v1 * inv2;
    dst[2] = v2 * inv2;
    dst[3] = v3 * inv2;

    if (gtid == 0)
        out[OFF_LOSS] = g_loss * (1.0f / (float)(N_VEC * CDIM));
}

// ---------------------------------------------------------------------------
extern "C" void kernel_launch(void* const* d_in, const int* in_sizes, int n_in,
                              void* d_out, int out_size) {
    const float* z   = (const float*)d_in[0];
    const float* emb = (const float*)d_in[1];
    const float* csz = (const float*)d_in[2];
    float* out = (float*)d_out;

    cudaFuncSetAttribute(k_mma, cudaFuncAttributeMaxDynamicSharedMemorySize, SMEM_TOTAL);

    k_prep<<<NORM_BLKS + ESPL_BLKS + TRNS_BLKS + ZERO_BLKS, 256>>>(z, emb);  // 0
    dim3 grid_mma(N_VEC / 128, KSPL);
    k_mma<<<grid_mma, 256, SMEM_TOTAL>>>();                                  // 1
    k_merge<<<N_VEC / 256, 256>>>();                                         // 2
    k_fixup<<<FIX_SLOTS * 32, 128>>>();                                      // 3 <- ncu
    k_scatter<<<(N_VEC * CDIM) / 256, 256>>>(emb, out);                      // 4
    k_update<<<(N_TOK * CDIM / 4) / 256, 256>>>(emb, csz, out);              // 5
}

// round 16
// speedup vs baseline: 1.0228x; 1.0228x over previous
#include <cuda_runtime.h>
#include <cstdint>

// ---------------------------------------------------------------------------
// NormEMAVectorQuantizer (sm_103a via compute_103) — round 16
// TF32 mma.sync screen + gap test + exact fp32 fixup (4 q/block spread).
//   out = concat( z_q[262144], loss[1], token_ids[8192],
//                 new_embedding[262144], new_cluster_sizes[8192] ) = 540673 f32
// ---------------------------------------------------------------------------

#define N_VEC   8192
#define N_TOK   8192
#define CDIM    32
#define KSPL    16
#define THRESH  2.0e-3f     // >= 2 * 2^-10 rigorous tf32 dot-error bound (unit vecs)

#define OFF_ZQ    0
#define OFF_LOSS  262144
#define OFF_TOK   262145
#define OFF_EMB   270337
#define OFF_CSZ   532481

// B layout: per code 44 words (32 tf32 frag-packed -> 2x LDS.128 per chain)
#define EPKW        44
#define CODE_BYTES  176
#define NB_CODES    128
#define STAGE_BYTES (NB_CODES * CODE_BYTES)   // 22528
#define SMEM_TOTAL  (2 * STAGE_BYTES)         // 45056

// scratch (__device__ globals; no allocations allowed)
__device__ float              g_zn[N_VEC * CDIM];
__device__ uint32_t           g_qpk[N_VEC * CDIM];
__device__ uint32_t           g_epk[N_TOK * EPKW];
__device__ float              g_ekT[CDIM * N_TOK];     // fp32 codes, TRANSPOSED
__device__ unsigned long long g_t1[KSPL * N_VEC];
__device__ float              g_t2v[KSPL * N_VEC];
__device__ unsigned long long g_key[N_VEC];
__device__ int                g_fix[N_VEC];
__device__ int                g_nfix;
__device__ float              g_bins[N_TOK];
__device__ float              g_esum[N_TOK * CDIM];
__device__ float              g_loss;

// ---------------- helpers ---------------------------------------------------
static __device__ __forceinline__ uint32_t smem_u32(const void* p) {
    uint32_t a;
    asm("{ .reg .u64 t; cvta.to.shared.u64 t, %1; cvt.u32.u64 %0, t; }" : "=r"(a) : "l"(p));
    return a;
}
static __device__ __forceinline__ unsigned int ordered_u32(float v) {
    unsigned int b = __float_as_uint(v);
    return (b & 0x80000000u) ? ~b : (b | 0x80000000u);
}
static __device__ __forceinline__ float unordered_f32(unsigned int u) {
    unsigned int b = (u & 0x80000000u) ? (u & 0x7fffffffu) : ~u;
    return __uint_as_float(b);
}
static __device__ __forceinline__ uint32_t to_tf32(float x) {
    uint32_t r;
    asm("cvt.rna.tf32.f32 %0, %1;" : "=r"(r) : "f"(x));
    return r;
}
// frag-packed position: thread l4 consumes words [l4*8 .. l4*8+7]
static __device__ __forceinline__ int b_reorder(int c) {
    int kc = c >> 3, r = c & 7;
    return (r < 4) ? (r * 8 + kc * 2) : ((r - 4) * 8 + kc * 2 + 1);
}

#define MMA_TF32(D, Af, Bf)                                                   \
    asm volatile(                                                             \
        "mma.sync.aligned.m16n8k8.row.col.f32.tf32.tf32.f32 "                 \
        "{%0,%1,%2,%3}, {%4,%5,%6,%7}, {%8,%9}, {%0,%1,%2,%3};"               \
        : "+f"((D)[0]), "+f"((D)[1]), "+f"((D)[2]), "+f"((D)[3])              \
        : "r"((Af)[0]), "r"((Af)[1]), "r"((Af)[2]), "r"((Af)[3]),             \
          "r"((Bf)[0]), "r"((Bf)[1]))

// ---------------------------------------------------------------------------
// K1: fused prep — L2norm(z)+tf32 pack | embedding frag-pack | fp32
//     transpose | zero scratch.
// ---------------------------------------------------------------------------
#define NORM_BLKS 1024
#define ESPL_BLKS 1024
#define TRNS_BLKS 32
#define ZERO_ITEMS (N_TOK * CDIM + N_TOK)
#define ZERO_BLKS ((ZERO_ITEMS + 255) / 256)

__global__ __launch_bounds__(256) void k_prep(const float* __restrict__ z,
                                              const float* __restrict__ emb) {
    __shared__ float tile[256][33];
    if (blockIdx.x < NORM_BLKS) {
        int warp = threadIdx.x >> 5;
        int lane = threadIdx.x & 31;                 // channel c
        int n    = blockIdx.x * 8 + warp;
        int b    = n >> 8, hw = n & 255;
        float v  = z[b * (CDIM * 256) + lane * 256 + hw];
        float ss = v * v;
#pragma unroll
        for (int o = 16; o > 0; o >>= 1)
            ss += __shfl_xor_sync(0xffffffffu, ss, o);
        float inv = 1.0f / fmaxf(sqrtf(ss), 1e-12f);
        float x = v * inv;
        g_zn[n * CDIM + lane]  = x;
        g_qpk[n * CDIM + lane] = to_tf32(x);
    } else if (blockIdx.x < NORM_BLKS + ESPL_BLKS) {
        int i = (blockIdx.x - NORM_BLKS) * 256 + threadIdx.x;   // 0..262143
        int r = i >> 5, c = i & 31;
        g_epk[r * EPKW + b_reorder(c)] = to_tf32(emb[i]);
    } else if (blockIdx.x < NORM_BLKS + ESPL_BLKS + TRNS_BLKS) {
        int j = blockIdx.x - (NORM_BLKS + ESPL_BLKS);
        int rbase = j * 256;
#pragma unroll 4
        for (int jj = 0; jj < 32; jj++) {
            int idx = jj * 256 + threadIdx.x;         // coalesced read
            tile[idx >> 5][idx & 31] = emb[rbase * 32 + idx];
        }
        __syncthreads();
#pragma unroll
        for (int jj = 0; jj < 4; jj++) {
            int c = jj * 8 + (threadIdx.x >> 5);
#pragma unroll
            for (int inner = 0; inner < 8; inner++) {
                int r = inner * 32 + (threadIdx.x & 31);
                g_ekT[c * N_TOK + rbase + r] = tile[r][c];   // coalesced write
            }
        }
    } else {
        int i = (blockIdx.x - NORM_BLKS - ESPL_BLKS - TRNS_BLKS) * 256 + threadIdx.x;
        if (i < N_TOK * CDIM) g_esum[i] = 0.0f;
        else if (i < ZERO_ITEMS) g_bins[i - N_TOK * CDIM] = 0.0f;
        if (i == 0) { g_loss = 0.0f; g_nfix = 0; }
    }
}

// ---------------------------------------------------------------------------
// K2: TF32 mma.sync screen, ILP-4 chains, LDS.128 frags, unroll-2.
// grid (64, 16) = 1024 CTAs.   (unchanged from R15 — at its mix ceiling)
// ---------------------------------------------------------------------------
__global__ __launch_bounds__(256, 3) void k_mma() {
    extern __shared__ uint32_t smem[];
    uint32_t sbase = smem_u32(smem);
    int tid = threadIdx.x, wid = tid >> 5, lane = tid & 31;
    int g4 = lane >> 2, l4 = lane & 3;
    int qb    = blockIdx.x * 128 + wid * 16;
    int kbase = blockIdx.y * (N_TOK / KSPL);

    uint32_t A[4][4];
    {
        const uint32_t* q0 = g_qpk + (qb + g4) * CDIM;
        const uint32_t* q8 = g_qpk + (qb + g4 + 8) * CDIM;
#pragma unroll
        for (int kc = 0; kc < 4; kc++) {
            int w = kc * 8 + l4;
            A[kc][0] = q0[w];
            A[kc][1] = q8[w];
            A[kc][2] = q0[w + 4];
            A[kc][3] = q8[w + 4];
        }
    }

    float v1a = -3.4e38f, v2a = -3.4e38f; int k1a = 0;
    float v1b = -3.4e38f, v2b = -3.4e38f; int k1b = 0;

    {
        const char* src = (const char*)g_epk + (size_t)kbase * CODE_BYTES;
#pragma unroll
        for (int j = 0; j < 6; j++) {
            int idx = tid + j * 256;
            if (idx < STAGE_BYTES / 16)
                asm volatile("cp.async.ca.shared.global [%0], [%1], 16;"
                             :: "r"(sbase + idx * 16), "l"(src + idx * 16) : "memory");
        }
        asm volatile("cp.async.commit_group;" ::: "memory");
    }

    for (int nb = 0; nb < (N_TOK / KSPL) / NB_CODES; nb++) {
        asm volatile("cp.async.wait_group 0;" ::: "memory");
        __syncthreads();
        if (nb + 1 < (N_TOK / KSPL) / NB_CODES) {
            const char* src = (const char*)g_epk +
                              (size_t)(kbase + (nb + 1) * NB_CODES) * CODE_BYTES;
            uint32_t dst = sbase + ((nb + 1) & 1) * STAGE_BYTES;
#pragma unroll
            for (int j = 0; j < 6; j++) {
                int idx = tid + j * 256;
                if (idx < STAGE_BYTES / 16)
                    asm volatile("cp.async.ca.shared.global [%0], [%1], 16;"
                                 :: "r"(dst + idx * 16), "l"(src + idx * 16) : "memory");
            }
            asm volatile("cp.async.commit_group;" ::: "memory");
        }

        const uint32_t* buf = smem + (nb & 1) * (STAGE_BYTES / 4);

#pragma unroll 2
        for (int nt = 0; nt < NB_CODES / 8; nt += 4) {
            const uint32_t* r0 = buf + (nt * 8 + g4) * EPKW + l4 * 8;
            float D0[4] = {0.f, 0.f, 0.f, 0.f};
            float D1[4] = {0.f, 0.f, 0.f, 0.f};
            float D2[4] = {0.f, 0.f, 0.f, 0.f};
            float D3[4] = {0.f, 0.f, 0.f, 0.f};
            uint4 p0a = *(const uint4*)(r0);
            uint4 p0b = *(const uint4*)(r0 + 4);
            uint4 p1a = *(const uint4*)(r0 + 8  * EPKW);
            uint4 p1b = *(const uint4*)(r0 + 8  * EPKW + 4);
            uint4 p2a = *(const uint4*)(r0 + 16 * EPKW);
            uint4 p2b = *(const uint4*)(r0 + 16 * EPKW + 4);
            uint4 p3a = *(const uint4*)(r0 + 24 * EPKW);
            uint4 p3b = *(const uint4*)(r0 + 24 * EPKW + 4);
            {
                uint32_t B0[2] = {p0a.x, p0a.y};
                uint32_t B1[2] = {p1a.x, p1a.y};
                uint32_t B2[2] = {p2a.x, p2a.y};
                uint32_t B3[2] = {p3a.x, p3a.y};
                MMA_TF32(D0, A[0], B0); MMA_TF32(D1, A[0], B1);
                MMA_TF32(D2, A[0], B2); MMA_TF32(D3, A[0], B3);
            }
            {
                uint32_t B0[2] = {p0a.z, p0a.w};
                uint32_t B1[2] = {p1a.z, p1a.w};
                uint32_t B2[2] = {p2a.z, p2a.w};
                uint32_t B3[2] = {p3a.z, p3a.w};
                MMA_TF32(D0, A[1], B0); MMA_TF32(D1, A[1], B1);
                MMA_TF32(D2, A[1], B2); MMA_TF32(D3, A[1], B3);
            }
            {
                uint32_t B0[2] = {p0b.x, p0b.y};
                uint32_t B1[2] = {p1b.x, p1b.y};
                uint32_t B2[2] = {p2b.x, p2b.y};
                uint32_t B3[2] = {p3b.x, p3b.y};
                MMA_TF32(D0, A[2], B0); MMA_TF32(D1, A[2], B1);
                MMA_TF32(D2, A[2], B2); MMA_TF32(D3, A[2], B3);
            }
            {
                uint32_t B0[2] = {p0b.z, p0b.w};
                uint32_t B1[2] = {p1b.z, p1b.w};
                uint32_t B2[2] = {p2b.z, p2b.w};
                uint32_t B3[2] = {p3b.z, p3b.w};
                MMA_TF32(D0, A[3], B0); MMA_TF32(D1, A[3], B1);
                MMA_TF32(D2, A[3], B2); MMA_TF32(D3, A[3], B3);
            }

            int c0 = kbase + nb * NB_CODES + nt * 8 + l4 * 2;
            {
                float m0 = fmaxf(D0[0], D0[1]);
                float m1 = fmaxf(D1[0], D1[1]);
                float m2 = fmaxf(D2[0], D2[1]);
                float m3 = fmaxf(D3[0], D3[1]);
                float vm = fmaxf(fmaxf(m0, m1), fmaxf(m2, m3));
                if (vm > v1a) {
                    float sec; int kk;
                    if (m0 == vm) {
                        sec = fmaxf(fminf(D0[0], D0[1]), fmaxf(m1, fmaxf(m2, m3)));
                        kk = (D0[0] == vm) ? c0 : c0 + 1;
                    } else if (m1 == vm) {
                        sec = fmaxf(fminf(D1[0], D1[1]), fmaxf(m0, fmaxf(m2, m3)));
                        kk = (D1[0] == vm) ? c0 + 8 : c0 + 9;
                    } else if (m2 == vm) {
                        sec = fmaxf(fminf(D2[0], D2[1]), fmaxf(m0, fmaxf(m1, m3)));
                        kk = (D2[0] == vm) ? c0 + 16 : c0 + 17;
                    } else {
                        sec = fmaxf(fminf(D3[0], D3[1]), fmaxf(m0, fmaxf(m1, m2)));
                        kk = (D3[0] == vm) ? c0 + 24 : c0 + 25;
                    }
                    v2a = fmaxf(fmaxf(v2a, v1a), sec);
                    v1a = vm; k1a = kk;
                } else {
                    v2a = fmaxf(v2a, vm);
                }
            }
            {
                float m0 = fmaxf(D0[2], D0[3]);
                float m1 = fmaxf(D1[2], D1[3]);
                float m2 = fmaxf(D2[2], D2[3]);
                float m3 = fmaxf(D3[2], D3[3]);
                float vm = fmaxf(fmaxf(m0, m1), fmaxf(m2, m3));
                if (vm > v1b) {
                    float sec; int kk;
                    if (m0 == vm) {
                        sec = fmaxf(fminf(D0[2], D0[3]), fmaxf(m1, fmaxf(m2, m3)));
                        kk = (D0[2] == vm) ? c0 : c0 + 1;
                    } else if (m1 == vm) {
                        sec = fmaxf(fminf(D1[2], D1[3]), fmaxf(m0, fmaxf(m2, m3)));
                        kk = (D1[2] == vm) ? c0 + 8 : c0 + 9;
                    } else if (m2 == vm) {
                        sec = fmaxf(fminf(D2[2], D2[3]), fmaxf(m0, fmaxf(m1, m3)));
                        kk = (D2[2] == vm) ? c0 + 16 : c0 + 17;
                    } else {
                        sec = fmaxf(fminf(D3[2], D3[3]), fmaxf(m0, fmaxf(m1, m2)));
                        kk = (D3[2] == vm) ? c0 + 24 : c0 + 25;
                    }
                    v2b = fmaxf(fmaxf(v2b, v1b), sec);
                    v1b = vm; k1b = kk;
                } else {
                    v2b = fmaxf(v2b, vm);
                }
            }
        }
    }

#pragma unroll
    for (int d = 1; d < 4; d <<= 1) {
        float ov1; int ok1; float ov2;
        ov1 = __shfl_xor_sync(0xffffffffu, v1a, d);
        ok1 = __shfl_xor_sync(0xffffffffu, k1a, d);
        ov2 = __shfl_xor_sync(0xffffffffu, v2a, d);
        {
            bool take = (ov1 > v1a) || (ov1 == v1a && ok1 < k1a);
            float lose = take ? v1a : ov1;
            v2a = fmaxf(fmaxf(v2a, ov2), lose);
            if (take) { v1a = ov1; k1a = ok1; }
        }
        ov1 = __shfl_xor_sync(0xffffffffu, v1b, d);
        ok1 = __shfl_xor_sync(0xffffffffu, k1b, d);
        ov2 = __shfl_xor_sync(0xffffffffu, v2b, d);
        {
            bool take = (ov1 > v1b) || (ov1 == v1b && ok1 < k1b);
            float lose = take ? v1b : ov1;
            v2b = fmaxf(fmaxf(v2b, ov2), lose);
            if (take) { v1b = ov1; k1b = ok1; }
        }
    }
    if (l4 == 0) {
        int q = qb + g4;
        int sp = blockIdx.y;
        g_t1[sp * N_VEC + q] =
            ((unsigned long long)ordered_u32(v1a) << 32) |
            (unsigned int)(N_TOK - 1 - k1a);
        g_t2v[sp * N_VEC + q] = v2a;
        g_t1[sp * N_VEC + q + 8] =
            ((unsigned long long)ordered_u32(v1b) << 32) |
            (unsigned int)(N_TOK - 1 - k1b);
        g_t2v[sp * N_VEC + q + 8] = v2b;
    }
}

// ---------------------------------------------------------------------------
// K3: merge KSPL splits' top-2, gap test, build fixup list
// ---------------------------------------------------------------------------
__global__ __launch_bounds__(256) void k_merge() {
    int n = blockIdx.x * 256 + threadIdx.x;
    unsigned long long win = 0ull;
    float v2 = -3.4e38f;
#pragma unroll
    for (int s = 0; s < KSPL; s++) {
        unsigned long long t = g_t1[s * N_VEC + n];
        float tv2 = g_t2v[s * N_VEC + n];
        if (t > win) {
            v2 = fmaxf(v2, unordered_f32((unsigned int)(win >> 32)));
            win = t;
        } else {
            v2 = fmaxf(v2, unordered_f32((unsigned int)(t >> 32)));
        }
        v2 = fmaxf(v2, tv2);
    }
    float v1 = unordered_f32((unsigned int)(win >> 32));
    if (v1 - v2 < THRESH) {
        g_key[n] = 0ull;
        int i = atomicAdd(&g_nfix, 1);
        g_fix[i] = n;
    } else {
        g_key[n] = win;
    }
}

// ---------------------------------------------------------------------------
// K4: exact fp32 rescan for flagged queries — SPREAD SHAPE.
// 4 queries/block x 256-code chunks: ~10x more active blocks at cnt~200.
// grid = FIX_SLOTS x 32 chunks; float shuffle-max + smem atomicMax merge.
// ---------------------------------------------------------------------------
#define FIX_SLOTS 96
#define FIX_QPB   4
__global__ __launch_bounds__(128) void k_fixup() {
    __shared__ int   qid[FIX_QPB];
    __shared__ float zq[FIX_QPB][32];
    __shared__ unsigned long long qbest[FIX_QPB];
    int cnt = g_nfix;
    int chunk = blockIdx.x & 31;
    int slot  = blockIdx.x >> 5;
    if (slot * FIX_QPB >= cnt) return;
    int t = threadIdx.x;

    int ka = chunk * 256 + t;
    int kb = ka + 128;
    float ra[CDIM], rb[CDIM];
#pragma unroll
    for (int c = 0; c < CDIM; c++) {
        ra[c] = g_ekT[c * N_TOK + ka];     // lane-consecutive: coalesced
        rb[c] = g_ekT[c * N_TOK + kb];
    }

    for (int qg = slot * FIX_QPB; qg < cnt; qg += FIX_SLOTS * FIX_QPB) {
        int nq = cnt - qg;
        if (nq > FIX_QPB) nq = FIX_QPB;
        if (t < FIX_QPB) {
            qid[t]   = (t < nq) ? g_fix[qg + t] : -1;
            qbest[t] = 0ull;
        }
        __syncthreads();
        {   // 4 x 32 = 128 floats, one per thread, coalesced per-warp
            int q = t >> 5, c = t & 31;
            int n = qid[q];
            zq[q][c] = (n >= 0) ? g_zn[n * CDIM + c] : 0.0f;
        }
        __syncthreads();

#pragma unroll
        for (int q = 0; q < FIX_QPB; q += 2) {
            float sa0 = 0.f, sa1 = 0.f, sb0 = 0.f, sb1 = 0.f;
            const float4* zA = (const float4*)zq[q];
            const float4* zB = (const float4*)zq[q + 1];
#pragma unroll
            for (int c4 = 0; c4 < 8; c4++) {
                float4 za = zA[c4];
                float4 zb = zB[c4];
                int c = c4 * 4;
                sa0 = fmaf(za.x, ra[c], fmaf(za.y, ra[c+1],
                      fmaf(za.z, ra[c+2], fmaf(za.w, ra[c+3], sa0))));
                sa1 = fmaf(za.x, rb[c], fmaf(za.y, rb[c+1],
                      fmaf(za.z, rb[c+2], fmaf(za.w, rb[c+3], sa1))));
                sb0 = fmaf(zb.x, ra[c], fmaf(zb.y, ra[c+1],
                      fmaf(zb.z, ra[c+2], fmaf(zb.w, ra[c+3], sb0))));
                sb1 = fmaf(zb.x, rb[c], fmaf(zb.y, rb[c+1],
                      fmaf(zb.z, rb[c+2], fmaf(zb.w, rb[c+3], sb1))));
            }
            // query q reduction: float shuffle-max, then key atomic from winners
            float vA = fmaxf(sa0, sa1);
            int   kA = (sa1 > sa0) ? kb : ka;
            float mA = vA;
#pragma unroll
            for (int o = 16; o > 0; o >>= 1)
                mA = fmaxf(mA, __shfl_xor_sync(0xffffffffu, mA, o));
            if (vA == mA) {
                unsigned long long key =
                    ((unsigned long long)ordered_u32(vA) << 32) |
                    (unsigned int)(N_TOK - 1 - kA);
                atomicMax(&qbest[q], key);
            }
            float vB = fmaxf(sb0, sb1);
            int   kB = (sb1 > sb0) ? kb : ka;
            float mB = vB;
#pragma unroll
            for (int o = 16; o > 0; o >>= 1)
                mB = fmaxf(mB, __shfl_xor_sync(0xffffffffu, mB, o));
            if (vB == mB) {
                unsigned long long key =
                    ((unsigned long long)ordered_u32(vB) << 32) |
                    (unsigned int)(N_TOK - 1 - kB);
                atomicMax(&qbest[q + 1], key);
            }
        }
        __syncthreads();
        if (t < FIX_QPB && qid[t] >= 0)
            atomicMax(&g_key[qid[t]], qbest[t]);
        __syncthreads();
    }
}

// ---------------------------------------------------------------------------
// K5: scatter epilogue over 262144 threads
// ---------------------------------------------------------------------------
__global__ __launch_bounds__(256) void k_scatter(const float* __restrict__ emb,
                                                 float* __restrict__ out) {
    __shared__ float red[8];
    int g  = blockIdx.x * 256 + threadIdx.x;
    int b  = g >> 13;
    int c  = (g >> 8) & 31;
    int hw = g & 255;
    int n  = b * 256 + hw;

    unsigned long long key = g_key[n];
    int bi = (N_TOK - 1) - (int)(unsigned int)(key & 0xffffffffu);

    float ev = emb[bi * CDIM + c];
    float zv = g_zn[n * CDIM + c];
    out[OFF_ZQ + g] = ev;
    if (c == 0) {
        out[OFF_TOK + n] = (float)bi;
        atomicAdd(&g_bins[bi], 1.0f);
    }
    atomicAdd(&g_esum[bi * CDIM + c], zv);

    float d = ev - zv;
    float lsum = d * d;
#pragma unroll
    for (int o = 16; o > 0; o >>= 1)
        lsum += __shfl_xor_sync(0xffffffffu, lsum, o);
    if ((threadIdx.x & 31) == 0) red[threadIdx.x >> 5] = lsum;
    __syncthreads();
    if (threadIdx.x == 0) {
        float s = 0.0f;
#pragma unroll
        for (int w = 0; w < 8; w++) s += red[w];
        atomicAdd(&g_loss, s);
    }
}

// ---------------------------------------------------------------------------
// K6: EMA codebook update, 8 threads/token (float4), + loss write
// ---------------------------------------------------------------------------
__global__ __launch_bounds__(256) void k_update(const float* __restrict__ emb,
                                                const float* __restrict__ csz,
                                                float* __restrict__ out) {
    int gtid = blockIdx.x * 256 + threadIdx.x;   // 65536 threads
    int k  = gtid >> 3;
    int l8 = gtid & 7;

    float bcount = g_bins[k];
    if (l8 == 0)
        out[OFF_CSZ + k] = csz[k] * 0.99f + 0.01f * bcount;

    bool  zero  = (bcount == 0.0f);
    float invbc = 1.0f / (zero ? 1.0f : bcount);
    float4 e4   = *(const float4*)(g_esum + k * CDIM + l8 * 4);
    float m0 = e4.x * invbc, m1 = e4.y * invbc, m2 = e4.z * invbc, m3 = e4.w * invbc;
    float ss = m0 * m0 + m1 * m1 + m2 * m2 + m3 * m3;
    ss += __shfl_xor_sync(0xffffffffu, ss, 1);
    ss += __shfl_xor_sync(0xffffffffu, ss, 2);
    ss += __shfl_xor_sync(0xffffffffu, ss, 4);
    float inv = 1.0f / fmaxf(sqrtf(ss), 1e-12f);

    float4 ev4 = *(const float4*)(emb + k * CDIM + l8 * 4);
    float en0 = zero ? ev4.x : m0 * inv;
    float en1 = zero ? ev4.y : m1 * inv;
    float en2 = zero ? ev4.z : m2 * inv;
    float en3 = zero ? ev4.w : m3 * inv;

    float v0 = ev4.x * 0.99f + 0.01f * en0;
    float v1 = ev4.y * 0.99f + 0.01f * en1;
    float v2 = ev4.z * 0.99f + 0.01f * en2;
    float v3 = ev4.w * 0.99f + 0.01f * en3;
    float s2 = v0 * v0 + v1 * v1 + v2 * v2 + v3 * v3;
    s2 += __shfl_xor_sync(0xffffffffu, s2, 1);
    s2 += __shfl_xor_sync(0xffffffffu, s2, 2);
    s2 += __shfl_xor_sync(0xffffffffu, s2, 4);
    float inv2 = 1.0f / fmaxf(sqrtf(s2), 1e-12f);

    float* dst = out + OFF_EMB + k * CDIM + l8 * 4;   // OFF_EMB odd: scalar stores
    dst[0] = v0 * inv2;
    dst[1] = v1 * inv2;
    dst[2] = v2 * inv2;
    dst[3] = v3 * inv2;

    if (gtid == 0)
        out[OFF_LOSS] = g_loss * (1.0f / (float)(N_VEC * CDIM));
}

// ---------------------------------------------------------------------------
extern "C" void kernel_launch(void* const* d_in, const int* in_sizes, int n_in,
                              void* d_out, int out_size) {
    const float* z   = (const float*)d_in[0];
    const float* emb = (const float*)d_in[1];
    const float* csz = (const float*)d_in[2];
    float* out = (float*)d_out;

    cudaFuncSetAttribute(k_mma, cudaFuncAttributeMaxDynamicSharedMemorySize, SMEM_TOTAL);

    k_prep<<<NORM_BLKS + ESPL_BLKS + TRNS_BLKS + ZERO_BLKS, 256>>>(z, emb);  // 0
    dim3 grid_mma(N_VEC / 128, KSPL);
    k_mma<<<grid_mma, 256, SMEM_TOTAL>>>();                                  // 1
    k_merge<<<N_VEC / 256, 256>>>();                                         // 2
    k_fixup<<<FIX_SLOTS * 32, 128>>>();                                      // 3 <- ncu
    k_scatter<<<(N_VEC * CDIM) / 256, 256>>>(emb, out);                      // 4
    k_update<<<(N_TOK * CDIM / 4) / 256, 256>>>(emb, csz, out);              // 5
}

// round 17
// speedup vs baseline: 1.0496x; 1.0262x over previous
#include <cuda_runtime.h>
#include <cstdint>

// ---------------------------------------------------------------------------
// NormEMAVectorQuantizer (sm_103a via compute_103) — round 17
// TF32 mma.sync screen + gap test + exact fp32 fixup (redux.sync reduction).
//   out = concat( z_q[262144], loss[1], token_ids[8192],
//                 new_embedding[262144], new_cluster_sizes[8192] ) = 540673 f32
// ---------------------------------------------------------------------------

#define N_VEC   8192
#define N_TOK   8192
#define CDIM    32
#define KSPL    16
#define THRESH  2.0e-3f     // >= 2 * 2^-10 rigorous tf32 dot-error bound (unit vecs)

#define OFF_ZQ    0
#define OFF_LOSS  262144
#define OFF_TOK   262145
#define OFF_EMB   270337
#define OFF_CSZ   532481

// B layout: per code 44 words (32 tf32 frag-packed -> 2x LDS.128 per chain)
#define EPKW        44
#define CODE_BYTES  176
#define NB_CODES    128
#define STAGE_BYTES (NB_CODES * CODE_BYTES)   // 22528
#define SMEM_TOTAL  (2 * STAGE_BYTES)         // 45056

// scratch (__device__ globals; no allocations allowed)
__device__ float              g_zn[N_VEC * CDIM];
__device__ uint32_t           g_qpk[N_VEC * CDIM];
__device__ uint32_t           g_epk[N_TOK * EPKW];
__device__ float              g_ekT[CDIM * N_TOK];     // fp32 codes, TRANSPOSED
__device__ unsigned long long g_t1[KSPL * N_VEC];
__device__ float              g_t2v[KSPL * N_VEC];
__device__ unsigned long long g_key[N_VEC];
__device__ int                g_fix[N_VEC];
__device__ int                g_nfix;
__device__ float              g_bins[N_TOK];
__device__ float              g_esum[N_TOK * CDIM];
__device__ float              g_loss;

// ---------------- helpers ---------------------------------------------------
static __device__ __forceinline__ uint32_t smem_u32(const void* p) {
    uint32_t a;
    asm("{ .reg .u64 t; cvta.to.shared.u64 t, %1; cvt.u32.u64 %0, t; }" : "=r"(a) : "l"(p));
    return a;
}
static __device__ __forceinline__ unsigned int ordered_u32(float v) {
    unsigned int b = __float_as_uint(v);
    return (b & 0x80000000u) ? ~b : (b | 0x80000000u);
}
static __device__ __forceinline__ float unordered_f32(unsigned int u) {
    unsigned int b = (u & 0x80000000u) ? (u & 0x7fffffffu) : ~u;
    return __uint_as_float(b);
}
static __device__ __forceinline__ uint32_t to_tf32(float x) {
    uint32_t r;
    asm("cvt.rna.tf32.f32 %0, %1;" : "=r"(r) : "f"(x));
    return r;
}
static __device__ __forceinline__ uint32_t redux_max_u32(uint32_t v) {
    uint32_t r;
    asm("redux.sync.max.u32 %0, %1, 0xffffffff;" : "=r"(r) : "r"(v));
    return r;
}
// frag-packed position: thread l4 consumes words [l4*8 .. l4*8+7]
static __device__ __forceinline__ int b_reorder(int c) {
    int kc = c >> 3, r = c & 7;
    return (r < 4) ? (r * 8 + kc * 2) : ((r - 4) * 8 + kc * 2 + 1);
}

#define MMA_TF32(D, Af, Bf)                                                   \
    asm volatile(                                                             \
        "mma.sync.aligned.m16n8k8.row.col.f32.tf32.tf32.f32 "                 \
        "{%0,%1,%2,%3}, {%4,%5,%6,%7}, {%8,%9}, {%0,%1,%2,%3};"               \
        : "+f"((D)[0]), "+f"((D)[1]), "+f"((D)[2]), "+f"((D)[3])              \
        : "r"((Af)[0]), "r"((Af)[1]), "r"((Af)[2]), "r"((Af)[3]),             \
          "r"((Bf)[0]), "r"((Bf)[1]))

// ---------------------------------------------------------------------------
// K1: fused prep — L2norm(z)+tf32 pack | embedding frag-pack | fp32
//     transpose (spread: 128 blocks x 64 rows) | zero scratch.
// ---------------------------------------------------------------------------
#define NORM_BLKS 1024
#define ESPL_BLKS 1024
#define TRNS_BLKS 128
#define TRNS_ROWS 64
#define ZERO_ITEMS (N_TOK * CDIM + N_TOK)
#define ZERO_BLKS ((ZERO_ITEMS + 255) / 256)

__global__ __launch_bounds__(256) void k_prep(const float* __restrict__ z,
                                              const float* __restrict__ emb) {
    __shared__ float tile[TRNS_ROWS][33];
    if (blockIdx.x < NORM_BLKS) {
        int warp = threadIdx.x >> 5;
        int lane = threadIdx.x & 31;                 // channel c
        int n    = blockIdx.x * 8 + warp;
        int b    = n >> 8, hw = n & 255;
        float v  = z[b * (CDIM * 256) + lane * 256 + hw];
        float ss = v * v;
#pragma unroll
        for (int o = 16; o > 0; o >>= 1)
            ss += __shfl_xor_sync(0xffffffffu, ss, o);
        float inv = 1.0f / fmaxf(sqrtf(ss), 1e-12f);
        float x = v * inv;
        g_zn[n * CDIM + lane]  = x;
        g_qpk[n * CDIM + lane] = to_tf32(x);
    } else if (blockIdx.x < NORM_BLKS + ESPL_BLKS) {
        int i = (blockIdx.x - NORM_BLKS) * 256 + threadIdx.x;   // 0..262143
        int r = i >> 5, c = i & 31;
        g_epk[r * EPKW + b_reorder(c)] = to_tf32(emb[i]);
    } else if (blockIdx.x < NORM_BLKS + ESPL_BLKS + TRNS_BLKS) {
        int j = blockIdx.x - (NORM_BLKS + ESPL_BLKS);
        int rbase = j * TRNS_ROWS;
#pragma unroll
        for (int jj = 0; jj < 8; jj++) {
            int idx = jj * 256 + threadIdx.x;         // 0..2047, coalesced read
            tile[idx >> 5][idx & 31] = emb[rbase * 32 + idx];
        }
        __syncthreads();
#pragma unroll
        for (int jj = 0; jj < 4; jj++) {
            int c = jj * 8 + (threadIdx.x >> 5);
#pragma unroll
            for (int inner = 0; inner < 2; inner++) {
                int r = inner * 32 + (threadIdx.x & 31);
                g_ekT[c * N_TOK + rbase + r] = tile[r][c];   // coalesced write
            }
        }
    } else {
        int i = (blockIdx.x - NORM_BLKS - ESPL_BLKS - TRNS_BLKS) * 256 + threadIdx.x;
        if (i < N_TOK * CDIM) g_esum[i] = 0.0f;
        else if (i < ZERO_ITEMS) g_bins[i - N_TOK * CDIM] = 0.0f;
        if (i == 0) { g_loss = 0.0f; g_nfix = 0; }
    }
}

// ---------------------------------------------------------------------------
// K2: TF32 mma.sync screen, ILP-4 chains, LDS.128 frags, unroll-2.
// grid (64, 16) = 1024 CTAs.   (frozen — at its HMMA-mix ceiling)
// ---------------------------------------------------------------------------
__global__ __launch_bounds__(256, 3) void k_mma() {
    extern __shared__ uint32_t smem[];
    uint32_t sbase = smem_u32(smem);
    int tid = threadIdx.x, wid = tid >> 5, lane = tid & 31;
    int g4 = lane >> 2, l4 = lane & 3;
    int qb    = blockIdx.x * 128 + wid * 16;
    int kbase = blockIdx.y * (N_TOK / KSPL);

    uint32_t A[4][4];
    {
        const uint32_t* q0 = g_qpk + (qb + g4) * CDIM;
        const uint32_t* q8 = g_qpk + (qb + g4 + 8) * CDIM;
#pragma unroll
        for (int kc = 0; kc < 4; kc++) {
            int w = kc * 8 + l4;
            A[kc][0] = q0[w];
            A[kc][1] = q8[w];
            A[kc][2] = q0[w + 4];
            A[kc][3] = q8[w + 4];
        }
    }

    float v1a = -3.4e38f, v2a = -3.4e38f; int k1a = 0;
    float v1b = -3.4e38f, v2b = -3.4e38f; int k1b = 0;

    {
        const char* src = (const char*)g_epk + (size_t)kbase * CODE_BYTES;
#pragma unroll
        for (int j = 0; j < 6; j++) {
            int idx = tid + j * 256;
            if (idx < STAGE_BYTES / 16)
                asm volatile("cp.async.ca.shared.global [%0], [%1], 16;"
                             :: "r"(sbase + idx * 16), "l"(src + idx * 16) : "memory");
        }
        asm volatile("cp.async.commit_group;" ::: "memory");
    }

    for (int nb = 0; nb < (N_TOK / KSPL) / NB_CODES; nb++) {
        asm volatile("cp.async.wait_group 0;" ::: "memory");
        __syncthreads();
        if (nb + 1 < (N_TOK / KSPL) / NB_CODES) {
            const char* src = (const char*)g_epk +
                              (size_t)(kbase + (nb + 1) * NB_CODES) * CODE_BYTES;
            uint32_t dst = sbase + ((nb + 1) & 1) * STAGE_BYTES;
#pragma unroll
            for (int j = 0; j < 6; j++) {
                int idx = tid + j * 256;
                if (idx < STAGE_BYTES / 16)
                    asm volatile("cp.async.ca.shared.global [%0], [%1], 16;"
                                 :: "r"(dst + idx * 16), "l"(src + idx * 16) : "memory");
            }
            asm volatile("cp.async.commit_group;" ::: "memory");
        }

        const uint32_t* buf = smem + (nb & 1) * (STAGE_BYTES / 4);

#pragma unroll 2
        for (int nt = 0; nt < NB_CODES / 8; nt += 4) {
            const uint32_t* r0 = buf + (nt * 8 + g4) * EPKW + l4 * 8;
            float D0[4] = {0.f, 0.f, 0.f, 0.f};
            float D1[4] = {0.f, 0.f, 0.f, 0.f};
            float D2[4] = {0.f, 0.f, 0.f, 0.f};
            float D3[4] = {0.f, 0.f, 0.f, 0.f};
            uint4 p0a = *(const uint4*)(r0);
            uint4 p0b = *(const uint4*)(r0 + 4);
            uint4 p1a = *(const uint4*)(r0 + 8  * EPKW);
            uint4 p1b = *(const uint4*)(r0 + 8  * EPKW + 4);
            uint4 p2a = *(const uint4*)(r0 + 16 * EPKW);
            uint4 p2b = *(const uint4*)(r0 + 16 * EPKW + 4);
            uint4 p3a = *(const uint4*)(r0 + 24 * EPKW);
            uint4 p3b = *(const uint4*)(r0 + 24 * EPKW + 4);
            {
                uint32_t B0[2] = {p0a.x, p0a.y};
                uint32_t B1[2] = {p1a.x, p1a.y};
                uint32_t B2[2] = {p2a.x, p2a.y};
                uint32_t B3[2] = {p3a.x, p3a.y};
                MMA_TF32(D0, A[0], B0); MMA_TF32(D1, A[0], B1);
                MMA_TF32(D2, A[0], B2); MMA_TF32(D3, A[0], B3);
            }
            {
                uint32_t B0[2] = {p0a.z, p0a.w};
                uint32_t B1[2] = {p1a.z, p1a.w};
                uint32_t B2[2] = {p2a.z, p2a.w};
                uint32_t B3[2] = {p3a.z, p3a.w};
                MMA_TF32(D0, A[1], B0); MMA_TF32(D1, A[1], B1);
                MMA_TF32(D2, A[1], B2); MMA_TF32(D3, A[1], B3);
            }
            {
                uint32_t B0[2] = {p0b.x, p0b.y};
                uint32_t B1[2] = {p1b.x, p1b.y};
                uint32_t B2[2] = {p2b.x, p2b.y};
                uint32_t B3[2] = {p3b.x, p3b.y};
                MMA_TF32(D0, A[2], B0); MMA_TF32(D1, A[2], B1);
                MMA_TF32(D2, A[2], B2); MMA_TF32(D3, A[2], B3);
            }
            {
                uint32_t B0[2] = {p0b.z, p0b.w};
                uint32_t B1[2] = {p1b.z, p1b.w};
                uint32_t B2[2] = {p2b.z, p2b.w};
                uint32_t B3[2] = {p3b.z, p3b.w};
                MMA_TF32(D0, A[3], B0); MMA_TF32(D1, A[3], B1);
                MMA_TF32(D2, A[3], B2); MMA_TF32(D3, A[3], B3);
            }

            int c0 = kbase + nb * NB_CODES + nt * 8 + l4 * 2;
            {
                float m0 = fmaxf(D0[0], D0[1]);
                float m1 = fmaxf(D1[0], D1[1]);
                float m2 = fmaxf(D2[0], D2[1]);
                float m3 = fmaxf(D3[0], D3[1]);
                float vm = fmaxf(fmaxf(m0, m1), fmaxf(m2, m3));
                if (vm > v1a) {
                    float sec; int kk;
                    if (m0 == vm) {
                        sec = fmaxf(fminf(D0[0], D0[1]), fmaxf(m1, fmaxf(m2, m3)));
                        kk = (D0[0] == vm) ? c0 : c0 + 1;
                    } else if (m1 == vm) {
                        sec = fmaxf(fminf(D1[0], D1[1]), fmaxf(m0, fmaxf(m2, m3)));
                        kk = (D1[0] == vm) ? c0 + 8 : c0 + 9;
                    } else if (m2 == vm) {
                        sec = fmaxf(fminf(D2[0], D2[1]), fmaxf(m0, fmaxf(m1, m3)));
                        kk = (D2[0] == vm) ? c0 + 16 : c0 + 17;
                    } else {
                        sec = fmaxf(fminf(D3[0], D3[1]), fmaxf(m0, fmaxf(m1, m2)));
                        kk = (D3[0] == vm) ? c0 + 24 : c0 + 25;
                    }
                    v2a = fmaxf(fmaxf(v2a, v1a), sec);
                    v1a = vm; k1a = kk;
                } else {
                    v2a = fmaxf(v2a, vm);
                }
            }
            {
                float m0 = fmaxf(D0[2], D0[3]);
                float m1 = fmaxf(D1[2], D1[3]);
                float m2 = fmaxf(D2[2], D2[3]);
                float m3 = fmaxf(D3[2], D3[3]);
                float vm = fmaxf(fmaxf(m0, m1), fmaxf(m2, m3));
                if (vm > v1b) {
                    float sec; int kk;
                    if (m0 == vm) {
                        sec = fmaxf(fminf(D0[2], D0[3]), fmaxf(m1, fmaxf(m2, m3)));
                        kk = (D0[2] == vm) ? c0 : c0 + 1;
                    } else if (m1 == vm) {
                        sec = fmaxf(fminf(D1[2], D1[3]), fmaxf(m0, fmaxf(m2, m3)));
                        kk = (D1[2] == vm) ? c0 + 8 : c0 + 9;
                    } else if (m2 == vm) {
                        sec = fmaxf(fminf(D2[2], D2[3]), fmaxf(m0, fmaxf(m1, m3)));
                        kk = (D2[2] == vm) ? c0 + 16 : c0 + 17;
                    } else {
                        sec = fmaxf(fminf(D3[2], D3[3]), fmaxf(m0, fmaxf(m1, m2)));
                        kk = (D3[2] == vm) ? c0 + 24 : c0 + 25;
                    }
                    v2b = fmaxf(fmaxf(v2b, v1b), sec);
                    v1b = vm; k1b = kk;
                } else {
                    v2b = fmaxf(v2b, vm);
                }
            }
        }
    }

#pragma unroll
    for (int d = 1; d < 4; d <<= 1) {
        float ov1; int ok1; float ov2;
        ov1 = __shfl_xor_sync(0xffffffffu, v1a, d);
        ok1 = __shfl_xor_sync(0xffffffffu, k1a, d);
        ov2 = __shfl_xor_sync(0xffffffffu, v2a, d);
        {
            bool take = (ov1 > v1a) || (ov1 == v1a && ok1 < k1a);
            float lose = take ? v1a : ov1;
            v2a = fmaxf(fmaxf(v2a, ov2), lose);
            if (take) { v1a = ov1; k1a = ok1; }
        }
        ov1 = __shfl_xor_sync(0xffffffffu, v1b, d);
        ok1 = __shfl_xor_sync(0xffffffffu, k1b, d);
        ov2 = __shfl_xor_sync(0xffffffffu, v2b, d);
        {
            bool take = (ov1 > v1b) || (ov1 == v1b && ok1 < k1b);
            float lose = take ? v1b : ov1;
            v2b = fmaxf(fmaxf(v2b, ov2), lose);
            if (take) { v1b = ov1; k1b = ok1; }
        }
    }
    if (l4 == 0) {
        int q = qb + g4;
        int sp = blockIdx.y;
        g_t1[sp * N_VEC + q] =
            ((unsigned long long)ordered_u32(v1a) << 32) |
            (unsigned int)(N_TOK - 1 - k1a);
        g_t2v[sp * N_VEC + q] = v2a;
        g_t1[sp * N_VEC + q + 8] =
            ((unsigned long long)ordered_u32(v1b) << 32) |
            (unsigned int)(N_TOK - 1 - k1b);
        g_t2v[sp * N_VEC + q + 8] = v2b;
    }
}

// ---------------------------------------------------------------------------
// K3: merge KSPL splits' top-2, gap test, build fixup list
// ---------------------------------------------------------------------------
__global__ __launch_bounds__(256) void k_merge() {
    int n = blockIdx.x * 256 + threadIdx.x;
    unsigned long long win = 0ull;
    float v2 = -3.4e38f;
#pragma unroll
    for (int s = 0; s < KSPL; s++) {
        unsigned long long t = g_t1[s * N_VEC + n];
        float tv2 = g_t2v[s * N_VEC + n];
        if (t > win) {
            v2 = fmaxf(v2, unordered_f32((unsigned int)(win >> 32)));
            win = t;
        } else {
            v2 = fmaxf(v2, unordered_f32((unsigned int)(t >> 32)));
        }
        v2 = fmaxf(v2, tv2);
    }
    float v1 = unordered_f32((unsigned int)(win >> 32));
    if (v1 - v2 < THRESH) {
        g_key[n] = 0ull;
        int i = atomicAdd(&g_nfix, 1);
        g_fix[i] = n;
    } else {
        g_key[n] = win;
    }
}

// ---------------------------------------------------------------------------
// K4: exact fp32 rescan for flagged queries.
// grid 768 = 24 slots (16 q each) x 32 chunks (256 codes). Reduction via
// redux.sync.max.u32 (1 instr) + winner atomicMax (ties -> smallest k).
// ---------------------------------------------------------------------------
#define FIX_SLOTS 24
#define FIX_QPB   16
__global__ __launch_bounds__(128) void k_fixup() {
    __shared__ int   qid[FIX_QPB];
    __shared__ float zq[FIX_QPB][32];
    __shared__ unsigned long long qbest[FIX_QPB];
    int cnt = g_nfix;
    int chunk = blockIdx.x & 31;
    int slot  = blockIdx.x >> 5;
    if (slot * FIX_QPB >= cnt) return;
    int t = threadIdx.x;

    int ka = chunk * 256 + t;
    int kb = ka + 128;
    float ra[CDIM], rb[CDIM];
#pragma unroll
    for (int c = 0; c < CDIM; c++) {
        ra[c] = g_ekT[c * N_TOK + ka];     // lane-consecutive: coalesced
        rb[c] = g_ekT[c * N_TOK + kb];
    }

    for (int qg = slot * FIX_QPB; qg < cnt; qg += FIX_SLOTS * FIX_QPB) {
        int nq = cnt - qg;
        if (nq > FIX_QPB) nq = FIX_QPB;
        if (t < FIX_QPB) {
            qid[t]   = (t < nq) ? g_fix[qg + t] : -1;
            qbest[t] = 0ull;
        }
        __syncthreads();
#pragma unroll
        for (int j = 0; j < 4; j++) {
            int idx = t + j * 128;
            int q = idx >> 5, c = idx & 31;
            int n = qid[q];
            zq[q][c] = (n >= 0) ? g_zn[n * CDIM + c] : 0.0f;
        }
        __syncthreads();

#pragma unroll 1
        for (int q = 0; q < FIX_QPB; q += 2) {
            float sa0 = 0.f, sa1 = 0.f, sb0 = 0.f, sb1 = 0.f;
            const float4* zA = (const float4*)zq[q];
            const float4* zB = (const float4*)zq[q + 1];
#pragma unroll
            for (int c4 = 0; c4 < 8; c4++) {
                float4 za = zA[c4];
                float4 zb = zB[c4];
                int c = c4 * 4;
                sa0 = fmaf(za.x, ra[c], fmaf(za.y, ra[c+1],
                      fmaf(za.z, ra[c+2], fmaf(za.w, ra[c+3], sa0))));
                sa1 = fmaf(za.x, rb[c], fmaf(za.y, rb[c+1],
                      fmaf(za.z, rb[c+2], fmaf(za.w, rb[c+3], sa1))));
                sb0 = fmaf(zb.x, ra[c], fmaf(zb.y, ra[c+1],
                      fmaf(zb.z, ra[c+2], fmaf(zb.w, ra[c+3], sb0))));
                sb1 = fmaf(zb.x, rb[c], fmaf(zb.y, rb[c+1],
                      fmaf(zb.z, rb[c+2], fmaf(zb.w, rb[c+3], sb1))));
            }
            // query q: one-instruction warp max, winners commit key
            float vA = fmaxf(sa0, sa1);
            int   kA = (sa1 > sa0) ? kb : ka;
            uint32_t oA = ordered_u32(vA);
            uint32_t mA = redux_max_u32(oA);
            if (oA == mA) {
                unsigned long long key = ((unsigned long long)mA << 32) |
                                         (unsigned int)(N_TOK - 1 - kA);
                atomicMax(&qbest[q], key);
            }
            // query q+1
            float vB = fmaxf(sb0, sb1);
            int   kB = (sb1 > sb0) ? kb : ka;
            uint32_t oB = ordered_u32(vB);
            uint32_t mB = redux_max_u32(oB);
            if (oB == mB) {
                unsigned long long key = ((unsigned long long)mB << 32) |
                                         (unsigned int)(N_TOK - 1 - kB);
                atomicMax(&qbest[q + 1], key);
            }
        }
        __syncthreads();
        if (t < FIX_QPB && qid[t] >= 0)
            atomicMax(&g_key[qid[t]], qbest[t]);
        __syncthreads();
    }
}

// ---------------------------------------------------------------------------
// K5: scatter epilogue over 262144 threads
// ---------------------------------------------------------------------------
__global__ __launch_bounds__(256) void k_scatter(const float* __restrict__ emb,
                                                 float* __restrict__ out) {
    __shared__ float red[8];
    int g  = blockIdx.x * 256 + threadIdx.x;
    int b  = g >> 13;
    int c  = (g >> 8) & 31;
    int hw = g & 255;
    int n  = b * 256 + hw;

    unsigned long long key = g_key[n];
    int bi = (N_TOK - 1) - (int)(unsigned int)(key & 0xffffffffu);

    float ev = emb[bi * CDIM + c];
    float zv = g_zn[n * CDIM + c];
    out[OFF_ZQ + g] = ev;
    if (c == 0) {
        out[OFF_TOK + n] = (float)bi;
        atomicAdd(&g_bins[bi], 1.0f);
    }
    atomicAdd(&g_esum[bi * CDIM + c], zv);

    float d = ev - zv;
    float lsum = d * d;
#pragma unroll
    for (int o = 16; o > 0; o >>= 1)
        lsum += __shfl_xor_sync(0xffffffffu, lsum, o);
    if ((threadIdx.x & 31) == 0) red[threadIdx.x >> 5] = lsum;
    __syncthreads();
    if (threadIdx.x == 0) {
        float s = 0.0f;
#pragma unroll
        for (int w = 0; w < 8; w++) s += red[w];
        atomicAdd(&g_loss, s);
    }
}

// ---------------------------------------------------------------------------
// K6: EMA codebook update, 8 threads/token (float4), + loss write
// ---------------------------------------------------------------------------
__global__ __launch_bounds__(256) void k_update(const float* __restrict__ emb,
                                                const float* __restrict__ csz,
                                                float* __restrict__ out) {
    int gtid = blockIdx.x * 256 + threadIdx.x;   // 65536 threads
    int k  = gtid >> 3;
    int l8 = gtid & 7;

    float bcount = g_bins[k];
    if (l8 == 0)
        out[OFF_CSZ + k] = csz[k] * 0.99f + 0.01f * bcount;

    bool  zero  = (bcount == 0.0f);
    float invbc = 1.0f / (zero ? 1.0f : bcount);
    float4 e4   = *(const float4*)(g_esum + k * CDIM + l8 * 4);
    float m0 = e4.x * invbc, m1 = e4.y * invbc, m2 = e4.z * invbc, m3 = e4.w * invbc;
    float ss = m0 * m0 + m1 * m1 + m2 * m2 + m3 * m3;
    ss += __shfl_xor_sync(0xffffffffu, ss, 1);
    ss += __shfl_xor_sync(0xffffffffu, ss, 2);
    ss += __shfl_xor_sync(0xffffffffu, ss, 4);
    float inv = 1.0f / fmaxf(sqrtf(ss), 1e-12f);

    float4 ev4 = *(const float4*)(emb + k * CDIM + l8 * 4);
    float en0 = zero ? ev4.x : m0 * inv;
    float en1 = zero ? ev4.y : m1 * inv;
    float en2 = zero ? ev4.z : m2 * inv;
    float en3 = zero ? ev4.w : m3 * inv;

    float v0 = ev4.x * 0.99f + 0.01f * en0;
    float v1 = ev4.y * 0.99f + 0.01f * en1;
    float v2 = ev4.z * 0.99f + 0.01f * en2;
    float v3 = ev4.w * 0.99f + 0.01f * en3;
    float s2 = v0 * v0 + v1 * v1 + v2 * v2 + v3 * v3;
    s2 += __shfl_xor_sync(0xffffffffu, s2, 1);
    s2 += __shfl_xor_sync(0xffffffffu, s2, 2);
    s2 += __shfl_xor_sync(0xffffffffu, s2, 4);
    float inv2 = 1.0f / fmaxf(sqrtf(s2), 1e-12f);

    float* dst = out + OFF_EMB + k * CDIM + l8 * 4;
    dst[0] = v0 * inv2;
    dst[1] = v1 * inv2;
    dst[2] = v2 * inv2;
    dst[3] = v3 * inv2;

    if (gtid == 0)
        out[OFF_LOSS] = g_loss * (1.0f / (float)(N_VEC * CDIM));
}

// ---------------------------------------------------------------------------
extern "C" void kernel_launch(void* const* d_in, const int* in_sizes, int n_in,
                              void* d_out, int out_size) {
    const float* z   = (const float*)d_in[0];
    const float* emb = (const float*)d_in[1];
    const float* csz = (const float*)d_in[2];
    float* out = (float*)d_out;

    cudaFuncSetAttribute(k_mma, cudaFuncAttributeMaxDynamicSharedMemorySize, SMEM_TOTAL);

    k_prep<<<NORM_BLKS + ESPL_BLKS + TRNS_BLKS + ZERO_BLKS, 256>>>(z, emb);  // 0
    dim3 grid_mma(N_VEC / 128, KSPL);
    k_mma<<<grid_mma, 256, SMEM_TOTAL>>>();                                  // 1
    k_merge<<<N_VEC / 256, 256>>>();                                         // 2
    k_fixup<<<FIX_SLOTS * 32, 128>>>();                                      // 3 <- ncu
    k_scatter<<<(N_VEC * CDIM) / 256, 256>>>(emb, out);                      // 4
    k_update<<<(N_TOK * CDIM / 4) / 256, 256>>>(emb, csz, out);              // 5
}